// round 1
// baseline (speedup 1.0000x reference)
#include <cuda_runtime.h>
#include <math.h>

// Problem constants
#define GB 8
#define GH 16
#define GN 512
#define GD 64
#define DMODEL 1024

// Scratch (device globals; allocation-free rule)
__device__ float g_qkv[3][(size_t)GB * GH * GN * GD];        // (z,b,h,n,d)
__device__ float g_geob[(size_t)GB * GH * GN * GN];          // (b,h,i,j)  log(max(g,1e-6))
__device__ float g_att[(size_t)GB * GN * GH * GD];           // (b,n,h*64+d)

// ---------------------------------------------------------------------------
// SGEMM: C[m][c] = sum_k A[m][k] * W[c][k] + bias[c]
// M=4096, N=1024, K=1024 fixed. BM=BN=128, BK=8, 256 threads, 8x8 per thread.
// PERM=1: store to (b,h,n,d) layout; PERM=0: row-major.
// ---------------------------------------------------------------------------
template <int PERM>
__device__ __forceinline__ void sgemm_body(const float* __restrict__ A,
                                           const float* __restrict__ W,
                                           const float* __restrict__ bias,
                                           float* __restrict__ C) {
    constexpr int LDS = 132;  // 128 + 4 pad: conflict-free stores & aligned float4 reads
    __shared__ float As[8 * LDS];
    __shared__ float Ws[8 * LDS];

    const int tid = threadIdx.x;
    const int tx = tid & 15;
    const int ty = tid >> 4;
    const int rowBase = blockIdx.y * 128;
    const int colBase = blockIdx.x * 128;
    const int lrow = tid >> 1;        // 0..127
    const int lk = (tid & 1) * 4;     // 0 or 4

    const float* Ag = A + (size_t)(rowBase + lrow) * 1024 + lk;
    const float* Wg = W + (size_t)(colBase + lrow) * 1024 + lk;

    float acc[8][8];
#pragma unroll
    for (int i = 0; i < 8; i++)
#pragma unroll
        for (int j = 0; j < 8; j++) acc[i][j] = 0.f;

    for (int k0 = 0; k0 < 1024; k0 += 8) {
        const float4 av = *(const float4*)(Ag + k0);
        const float4 wv = *(const float4*)(Wg + k0);
        __syncthreads();
        As[(lk + 0) * LDS + lrow] = av.x;
        As[(lk + 1) * LDS + lrow] = av.y;
        As[(lk + 2) * LDS + lrow] = av.z;
        As[(lk + 3) * LDS + lrow] = av.w;
        Ws[(lk + 0) * LDS + lrow] = wv.x;
        Ws[(lk + 1) * LDS + lrow] = wv.y;
        Ws[(lk + 2) * LDS + lrow] = wv.z;
        Ws[(lk + 3) * LDS + lrow] = wv.w;
        __syncthreads();
#pragma unroll
        for (int kk = 0; kk < 8; kk++) {
            const float4 a0 = *(const float4*)&As[kk * LDS + ty * 8];
            const float4 a1 = *(const float4*)&As[kk * LDS + ty * 8 + 4];
            const float4 b0 = *(const float4*)&Ws[kk * LDS + tx * 8];
            const float4 b1 = *(const float4*)&Ws[kk * LDS + tx * 8 + 4];
            const float ar[8] = {a0.x, a0.y, a0.z, a0.w, a1.x, a1.y, a1.z, a1.w};
            const float br[8] = {b0.x, b0.y, b0.z, b0.w, b1.x, b1.y, b1.z, b1.w};
#pragma unroll
            for (int i = 0; i < 8; i++)
#pragma unroll
                for (int j = 0; j < 8; j++)
                    acc[i][j] = fmaf(ar[i], br[j], acc[i][j]);
        }
    }

#pragma unroll
    for (int i = 0; i < 8; i++) {
        const int r = rowBase + ty * 8 + i;
#pragma unroll
        for (int j = 0; j < 8; j++) {
            const int c = colBase + tx * 8 + j;
            const float val = acc[i][j] + bias[c];
            if (PERM) {
                const int bb = r >> 9, n = r & 511;
                const int h = c >> 6, d = c & 63;
                C[(((size_t)(bb * GH + h) * GN + n) << 6) + d] = val;
            } else {
                C[(size_t)r * 1024 + c] = val;
            }
        }
    }
}

__global__ __launch_bounds__(256, 2) void qkv_gemm_kernel(
    const float* __restrict__ q, const float* __restrict__ k, const float* __restrict__ v,
    const float* __restrict__ Wq, const float* __restrict__ Wk, const float* __restrict__ Wv,
    const float* __restrict__ bq, const float* __restrict__ bk, const float* __restrict__ bv) {
    const int z = blockIdx.z;
    const float* A = (z == 0) ? q : (z == 1) ? k : v;
    const float* W = (z == 0) ? Wq : (z == 1) ? Wk : Wv;
    const float* bs = (z == 0) ? bq : (z == 1) ? bk : bv;
    sgemm_body<1>(A, W, bs, g_qkv[z]);
}

__global__ __launch_bounds__(256, 2) void out_gemm_kernel(
    const float* __restrict__ Wo, const float* __restrict__ bo, float* __restrict__ out) {
    sgemm_body<0>(g_att, Wo, bo, out);
}

// ---------------------------------------------------------------------------
// Geometry bias: g[b,h,i,j] = relu(emb(i,j) . Wg[h] + bg[h]); store log(max(g,1e-6))
// One block per (i, b); 256 threads cover j = 0..511.
// ---------------------------------------------------------------------------
__global__ __launch_bounds__(256) void geom_bias_kernel(const float* __restrict__ boxes,
                                                        const float* __restrict__ Wgm,
                                                        const float* __restrict__ bgv) {
    __shared__ float scx[512], scy[512], siw[512], sih[512], slw[512], slh[512];
    __shared__ float sW[1024];
    __shared__ float sbg[16];

    const int tid = threadIdx.x;
    const int i = blockIdx.x;
    const int b = blockIdx.y;

    for (int j = tid; j < 512; j += 256) {
        const float4 bx = *(const float4*)&boxes[((size_t)b * 512 + j) * 4];
        const float cx = (bx.x + bx.z) * 0.5f;
        const float cy = (bx.y + bx.w) * 0.5f;
        const float w = (bx.z - bx.x) + 1.0f;
        const float hh = (bx.w - bx.y) + 1.0f;
        scx[j] = cx; scy[j] = cy;
        siw[j] = w;  sih[j] = hh;
        slw[j] = logf(w); slh[j] = logf(hh);
    }
    for (int t = tid; t < 1024; t += 256) sW[t] = Wgm[t];
    if (tid < 16) sbg[tid] = bgv[tid];
    __syncthreads();

    const float cxi = scx[i], cyi = scy[i];
    const float inv_wi = 1.0f / siw[i], inv_hi = 1.0f / sih[i];
    const float lwi = slw[i], lhi = slh[i];

    const float dimc[8] = {1.0f, 0.421696503f, 0.177827941f, 0.0749894209f,
                           0.0316227766f, 0.0133352143f, 0.00562341325f, 0.00237137371f};

    for (int j = tid; j < 512; j += 256) {
        float pos[4];
        pos[0] = logf(fmaxf(fabsf((cxi - scx[j]) * inv_wi), 1e-3f));
        pos[1] = logf(fmaxf(fabsf((cyi - scy[j]) * inv_hi), 1e-3f));
        pos[2] = lwi - slw[j];
        pos[3] = lhi - slh[j];

        float acc[16];
#pragma unroll
        for (int h = 0; h < 16; h++) acc[h] = sbg[h];

#pragma unroll
        for (int p = 0; p < 4; p++) {
            const float base = 100.0f * pos[p];
#pragma unroll
            for (int f = 0; f < 8; f++) {
                float s, c;
                sincosf(base * dimc[f], &s, &c);  // accurate version: args reach ~700 rad
                const float* wrow = &sW[p * 8 + f];
#pragma unroll
                for (int h = 0; h < 16; h++) {
                    acc[h] = fmaf(s, wrow[h * 64], acc[h]);
                    acc[h] = fmaf(c, wrow[h * 64 + 32], acc[h]);
                }
            }
        }
#pragma unroll
        for (int h = 0; h < 16; h++)
            g_geob[(((size_t)(b * GH + h) * GN + i) * GN) + j] = logf(fmaxf(acc[h], 1e-6f));
    }
}

// ---------------------------------------------------------------------------
// Attention: per (b,h,64-query tile). Scores tile kept in smem (64x516 padded),
// two tiled GEMM phases + warp-shuffle softmax.
// smem: sQt[64x68] + sKV[64x68] + sS[64x516]  = 166,912 bytes (dynamic)
// ---------------------------------------------------------------------------
#define ATTN_SMEM_BYTES ((64 * 68 * 2 + 64 * 516) * 4)

__global__ __launch_bounds__(256, 1) void attn_kernel() {
    extern __shared__ float sm[];
    float* sQ = sm;                 // [d][row], stride 68
    float* sKV = sm + 64 * 68;      // phase1: [d][col] stride 68; phase3: [k][d] stride 68
    float* sS = sm + 2 * 64 * 68;   // [row][j], stride 516

    const int tid = threadIdx.x;
    const int qt = blockIdx.x, h = blockIdx.y, b = blockIdx.z;
    const int bh = b * GH + h;
    const float* qb = g_qkv[0] + ((size_t)bh * GN + qt * 64) * GD;
    const float* kb = g_qkv[1] + (size_t)bh * GN * GD;
    const float* vb = g_qkv[2] + (size_t)bh * GN * GD;
    const float* gb = g_geob + ((size_t)bh * GN + qt * 64) * GN;

    // Load Q tile transposed
#pragma unroll 4
    for (int t = tid; t < 4096; t += 256) {
        const int r = t >> 6, d = t & 63;
        sQ[d * 68 + r] = qb[t];
    }

    const int tx = tid & 15, ty = tid >> 4;

    // Phase 1: S = QK^T/8 + geo-bias
    for (int kc = 0; kc < 8; kc++) {
        __syncthreads();
#pragma unroll 4
        for (int t = tid; t < 4096; t += 256) {
            const int r = t >> 6, d = t & 63;
            sKV[d * 68 + r] = kb[kc * 4096 + t];
        }
        __syncthreads();
        float acc[4][4];
#pragma unroll
        for (int i = 0; i < 4; i++)
#pragma unroll
            for (int j = 0; j < 4; j++) acc[i][j] = 0.f;
#pragma unroll
        for (int d = 0; d < 64; d++) {
            const float4 a = *(const float4*)&sQ[d * 68 + ty * 4];
            const float4 kv = *(const float4*)&sKV[d * 68 + tx * 4];
            const float ar[4] = {a.x, a.y, a.z, a.w};
            const float br[4] = {kv.x, kv.y, kv.z, kv.w};
#pragma unroll
            for (int i = 0; i < 4; i++)
#pragma unroll
                for (int j = 0; j < 4; j++)
                    acc[i][j] = fmaf(ar[i], br[j], acc[i][j]);
        }
#pragma unroll
        for (int i = 0; i < 4; i++) {
            const int r = ty * 4 + i;
            const float4 b4 = *(const float4*)&gb[(size_t)r * GN + kc * 64 + tx * 4];
            float* srow = &sS[r * 516 + kc * 64 + tx * 4];
            srow[0] = fmaf(acc[i][0], 0.125f, b4.x);
            srow[1] = fmaf(acc[i][1], 0.125f, b4.y);
            srow[2] = fmaf(acc[i][2], 0.125f, b4.z);
            srow[3] = fmaf(acc[i][3], 0.125f, b4.w);
        }
    }
    __syncthreads();

    // Phase 2: softmax rows (8 warps x 8 rows)
    {
        const int warp = tid >> 5, lane = tid & 31;
        for (int r = warp; r < 64; r += 8) {
            float* row = &sS[r * 516];
            float vals[16];
            float m = -1e30f;
#pragma unroll
            for (int t = 0; t < 16; t++) {
                vals[t] = row[lane + t * 32];
                m = fmaxf(m, vals[t]);
            }
#pragma unroll
            for (int o = 16; o > 0; o >>= 1) m = fmaxf(m, __shfl_xor_sync(0xffffffffu, m, o));
            float ssum = 0.f;
#pragma unroll
            for (int t = 0; t < 16; t++) {
                vals[t] = __expf(vals[t] - m);
                ssum += vals[t];
            }
#pragma unroll
            for (int o = 16; o > 0; o >>= 1) ssum += __shfl_xor_sync(0xffffffffu, ssum, o);
            const float inv = 1.0f / ssum;
#pragma unroll
            for (int t = 0; t < 16; t++) row[lane + t * 32] = vals[t] * inv;
        }
    }

    // Phase 3: O = P V
    float o4[4][4];
#pragma unroll
    for (int i = 0; i < 4; i++)
#pragma unroll
        for (int j = 0; j < 4; j++) o4[i][j] = 0.f;

    for (int kc = 0; kc < 8; kc++) {
        __syncthreads();
#pragma unroll 4
        for (int t = tid; t < 4096; t += 256) {
            const int r = t >> 6, d = t & 63;
            sKV[r * 68 + d] = vb[kc * 4096 + t];
        }
        __syncthreads();
#pragma unroll
        for (int kk = 0; kk < 64; kk++) {
            const float4 vv = *(const float4*)&sKV[kk * 68 + tx * 4];
            const float p0 = sS[(ty * 4 + 0) * 516 + kc * 64 + kk];
            const float p1 = sS[(ty * 4 + 1) * 516 + kc * 64 + kk];
            const float p2 = sS[(ty * 4 + 2) * 516 + kc * 64 + kk];
            const float p3 = sS[(ty * 4 + 3) * 516 + kc * 64 + kk];
            const float vr[4] = {vv.x, vv.y, vv.z, vv.w};
            const float pr[4] = {p0, p1, p2, p3};
#pragma unroll
            for (int i = 0; i < 4; i++)
#pragma unroll
                for (int j = 0; j < 4; j++)
                    o4[i][j] = fmaf(pr[i], vr[j], o4[i][j]);
        }
    }

    // Store to (b, n, h*64+d)
#pragma unroll
    for (int i = 0; i < 4; i++) {
        const int n = qt * 64 + ty * 4 + i;
        float4 res;
        res.x = o4[i][0]; res.y = o4[i][1]; res.z = o4[i][2]; res.w = o4[i][3];
        *(float4*)&g_att[((size_t)b * GN + n) * 1024 + h * 64 + tx * 4] = res;
    }
}

// ---------------------------------------------------------------------------
extern "C" void kernel_launch(void* const* d_in, const int* in_sizes, int n_in,
                              void* d_out, int out_size) {
    (void)in_sizes; (void)n_in; (void)out_size;
    const float* queries = (const float*)d_in[0];
    const float* keys    = (const float*)d_in[1];
    const float* values  = (const float*)d_in[2];
    const float* boxes   = (const float*)d_in[3];
    const float* Wq = (const float*)d_in[4];
    const float* bq = (const float*)d_in[5];
    const float* Wk = (const float*)d_in[6];
    const float* bk = (const float*)d_in[7];
    const float* Wv = (const float*)d_in[8];
    const float* bv = (const float*)d_in[9];
    const float* Wo = (const float*)d_in[10];
    const float* bo = (const float*)d_in[11];
    const float* Wg = (const float*)d_in[12];
    const float* bg = (const float*)d_in[13];
    float* out = (float*)d_out;

    cudaFuncSetAttribute(attn_kernel, cudaFuncAttributeMaxDynamicSharedMemorySize,
                         ATTN_SMEM_BYTES);

    qkv_gemm_kernel<<<dim3(8, 32, 3), 256>>>(queries, keys, values, Wq, Wk, Wv, bq, bk, bv);
    geom_bias_kernel<<<dim3(512, 8), 256>>>(boxes, Wg, bg);
    attn_kernel<<<dim3(8, 16, 8), 256, ATTN_SMEM_BYTES>>>();
    out_gemm_kernel<<<dim3(8, 32, 1), 256>>>(Wo, bo, out);
}